// round 4
// baseline (speedup 1.0000x reference)
#include <cuda_runtime.h>
#include <cuda_bf16.h>
#include <cstdint>

// RelativeAttention B=2,H=16,L=2048,D=64 fp32.
// mma.sync bf16 3-way-split flash attention; 2 CTAs/SM; exp fused into S loop.

#define LSEQ   2048
#define DH     64
#define BM     64
#define BN     64
#define NT     (LSEQ / BN)    // 32
#define NTHR   128
#define MAXREL 8
#define LOG2E  1.4426950408889634f

#define PITCH  144            // bytes per 64-bf16 row (128B data + 16B pad)
#define BUFHALF 36864         // 4 matrices * 64*144
#define OFF_BL  0
#define OFF_BUF 128
#define KHIB(b) (OFF_BUF + (b) * BUFHALF + 0)
#define KLOB(b) (OFF_BUF + (b) * BUFHALF + 9216)
#define VHIB(b) (OFF_BUF + (b) * BUFHALF + 18432)
#define VLOB(b) (OFF_BUF + (b) * BUFHALF + 27648)
#define SMEM_TOTAL (128 + 2 * BUFHALF)   // 73856 B per CTA (2 CTAs = 147.7KB/SM)

// ---------------- helpers ----------------
__device__ __forceinline__ uint32_t s2u(const void* p) {
    uint32_t a;
    asm("{ .reg .u64 t; cvta.to.shared.u64 t, %1; cvt.u32.u64 %0, t; }" : "=r"(a) : "l"(p));
    return a;
}
__device__ __forceinline__ uint32_t cvt2(float lo, float hi) {   // bf16x2(lo|hi)
    uint32_t d;
    asm("cvt.rn.bf16x2.f32 %0, %1, %2;" : "=r"(d) : "f"(hi), "f"(lo));
    return d;
}
__device__ __forceinline__ float bflo(uint32_t p) { return __int_as_float(p << 16); }
__device__ __forceinline__ float bfhi(uint32_t p) { return __int_as_float(p & 0xFFFF0000u); }

__device__ __forceinline__ void mma16816(float* c, const uint32_t* a, const uint32_t* b) {
    asm volatile(
        "mma.sync.aligned.m16n8k16.row.col.f32.bf16.bf16.f32 "
        "{%0,%1,%2,%3}, {%4,%5,%6,%7}, {%8,%9}, {%0,%1,%2,%3};"
        : "+f"(c[0]), "+f"(c[1]), "+f"(c[2]), "+f"(c[3])
        : "r"(a[0]), "r"(a[1]), "r"(a[2]), "r"(a[3]), "r"(b[0]), "r"(b[1]));
}
__device__ __forceinline__ void ldsm4(uint32_t* r, uint32_t addr) {
    asm volatile("ldmatrix.sync.aligned.m8n8.x4.shared.b16 {%0,%1,%2,%3}, [%4];"
                 : "=r"(r[0]), "=r"(r[1]), "=r"(r[2]), "=r"(r[3]) : "r"(addr));
}
__device__ __forceinline__ void ldsm4t(uint32_t* r, uint32_t addr) {
    asm volatile("ldmatrix.sync.aligned.m8n8.x4.trans.shared.b16 {%0,%1,%2,%3}, [%4];"
                 : "=r"(r[0]), "=r"(r[1]), "=r"(r[2]), "=r"(r[3]) : "r"(addr));
}
// exp2, FFMA-only, x in [-100, ~1]
__device__ __forceinline__ float exp2_fast(float x) {
    x = fmaxf(x, -100.0f);
    float t = x + 12582912.0f;
    float n = t - 12582912.0f;
    float f = x - n;
    float p = 0.0013333558f;
    p = fmaf(p, f, 0.0096181291f);
    p = fmaf(p, f, 0.0555041090f);
    p = fmaf(p, f, 0.2402265069f);
    p = fmaf(p, f, 0.6931471806f);
    p = fmaf(p, f, 1.0f);
    return __int_as_float(__float_as_int(p) + (__float_as_int(t) << 23));
}
__device__ __forceinline__ void split4(float4 v, uint32_t& h0, uint32_t& h1,
                                       uint32_t& l0, uint32_t& l1) {
    h0 = cvt2(v.x, v.y);
    h1 = cvt2(v.z, v.w);
    l0 = cvt2(v.x - bflo(h0), v.y - bfhi(h0));
    l1 = cvt2(v.z - bflo(h1), v.w - bfhi(h1));
}

// ---------------- kernel ----------------
__global__ void __launch_bounds__(NTHR, 2)
relattn_mma(const float* __restrict__ q, const float* __restrict__ k,
            const float* __restrict__ v, const float* __restrict__ bias,
            float* __restrict__ out) {
    extern __shared__ char smem[];
    const uint32_t sb = s2u(smem);
    float* bl = (float*)(smem + OFF_BL);

    const int tid  = threadIdx.x;
    const int wid  = tid >> 5;            // 0..3
    const int lane = tid & 31;
    const int head = blockIdx.y;
    const int q0   = blockIdx.x * BM;

    const float* qh = q + (size_t)head * LSEQ * DH;
    const float* kh = k + (size_t)head * LSEQ * DH;
    const float* vh = v + (size_t)head * LSEQ * DH;
    float*       oh = out + (size_t)head * LSEQ * DH;

    if (tid < 2 * MAXREL + 1)
        bl[tid] = (bias[tid] - 12.0f) * LOG2E;

    // ---- Q fragments (persistent hi/lo), warp rows q0 + wid*16 + ... ----
    const int row0 = q0 + wid * 16 + (lane >> 2);
    const int ccol = (lane & 3) * 2;
    uint32_t qH[4][4], qL[4][4];
#pragma unroll
    for (int s = 0; s < 4; ++s) {
        const int c = s * 16 + ccol;
        float2 x0 = *(const float2*)&qh[(size_t)row0 * DH + c];
        float2 x1 = *(const float2*)&qh[(size_t)(row0 + 8) * DH + c];
        float2 x2 = *(const float2*)&qh[(size_t)row0 * DH + c + 8];
        float2 x3 = *(const float2*)&qh[(size_t)(row0 + 8) * DH + c + 8];
        float4 a = make_float4(x0.x * 0.125f, x0.y * 0.125f, x1.x * 0.125f, x1.y * 0.125f);
        float4 b = make_float4(x2.x * 0.125f, x2.y * 0.125f, x3.x * 0.125f, x3.y * 0.125f);
        split4(a, qH[s][0], qH[s][1], qL[s][0], qL[s][1]);
        split4(b, qH[s][2], qH[s][3], qL[s][2], qL[s][3]);
    }

    // ---- staging: 128 threads; thread -> row tid>>1 (0..63), 32-col half ----
    const int skv = tid >> 1;
    const int sdq = (tid & 1) * 32;
    float4 st[8];                          // reused for K then V

#define GLOAD(base_, n0_) do {                                               \
        const float* p_ = (base_) + (size_t)((n0_) + skv) * DH + sdq;        \
        _Pragma("unroll") for (int i_ = 0; i_ < 8; ++i_)                     \
            st[i_] = *(const float4*)(p_ + i_ * 4);                          \
    } while (0)

#define SSTORE(hiOff_, loOff_) do {                                          \
        char* h_ = smem + (hiOff_); char* l_ = smem + (loOff_);              \
        const int rb_ = skv * PITCH;                                         \
        _Pragma("unroll") for (int i_ = 0; i_ < 8; ++i_) {                   \
            uint32_t h0, h1, l0, l1;                                         \
            split4(st[i_], h0, h1, l0, l1);                                  \
            int o_ = rb_ + (sdq + i_ * 4) * 2;                               \
            *(uint2*)(h_ + o_) = make_uint2(h0, h1);                         \
            *(uint2*)(l_ + o_) = make_uint2(l0, l1);                         \
        } } while (0)

    // prologue: stage tile 0 into buf 0
    GLOAD(kh, 0); SSTORE(KHIB(0), KLOB(0));
    GLOAD(vh, 0); SSTORE(VHIB(0), VLOB(0));

    const uint32_t laneK = (uint32_t)(((lane & 7) + ((lane >> 4) & 1) * 8) * PITCH
                                      + ((lane >> 3) & 1) * 16);
    const uint32_t laneV = (uint32_t)(((lane & 7) + ((lane >> 3) & 1) * 8) * PITCH
                                      + ((lane >> 4) & 1) * 16);

    float oc[8][4];
#pragma unroll
    for (int i = 0; i < 8; ++i)
#pragma unroll
        for (int j = 0; j < 4; ++j) oc[i][j] = 0.0f;
    float rs0 = 0.0f, rs1 = 0.0f;
    const int relbase = ccol - row0;

    for (int t = 0; t < NT; ++t) {
        const int n0 = t * BN;
        const int buf = t & 1;
        const int nbuf = buf ^ 1;

        __syncthreads();                        // buf staged for everyone

        if (t + 1 < NT) GLOAD(kh, n0 + BN);     // K(t+1) in flight under S MMAs

        // tile-uniform bias mode
        const int mx = n0 + BN - 1 - q0;
        const int mn = n0 - (q0 + BM - 1);
        const bool generic = (mx > -MAXREL) && (mn < MAXREL);
        const float blc = (mx <= -MAXREL) ? bl[0] : bl[2 * MAXREL];

        // ---- S = Q K^T fused with softmax: np-outer, s-inner ----
        uint32_t pH[4][4], pL[4][4];
#pragma unroll
        for (int np = 0; np < 4; ++np) {
            float sc0[4] = {0.f, 0.f, 0.f, 0.f};
            float sc1[4] = {0.f, 0.f, 0.f, 0.f};
#pragma unroll
            for (int s = 0; s < 4; ++s) {
                uint32_t bH[4], bL[4];
                uint32_t a = sb + (uint32_t)(np * 16 * PITCH + s * 32) + laneK;
                ldsm4(bH, a + KHIB(buf));
                ldsm4(bL, a + KLOB(buf));
                mma16816(sc0, qH[s], bH);
                mma16816(sc1, qH[s], bH + 2);
                mma16816(sc0, qL[s], bH);
                mma16816(sc1, qL[s], bH + 2);
                mma16816(sc0, qH[s], bL);
                mma16816(sc1, qH[s], bL + 2);
            }
            // exp for nt = 2np (sc0) and 2np+1 (sc1); overlaps next np's MMAs
#pragma unroll
            for (int h = 0; h < 2; ++h) {
                float* c = h ? sc1 : sc0;
                float e0, e1, e2, e3;
                if (generic) {
                    const int r0i = relbase + n0 + (2 * np + h) * 8;
                    const float b0 = bl[min(max(r0i,     -MAXREL), MAXREL) + MAXREL];
                    const float b1 = bl[min(max(r0i + 1, -MAXREL), MAXREL) + MAXREL];
                    const float b2 = bl[min(max(r0i - 8, -MAXREL), MAXREL) + MAXREL];
                    const float b3 = bl[min(max(r0i - 7, -MAXREL), MAXREL) + MAXREL];
                    e0 = exp2_fast(fmaf(c[0], LOG2E, b0));
                    e1 = exp2_fast(fmaf(c[1], LOG2E, b1));
                    e2 = exp2_fast(fmaf(c[2], LOG2E, b2));
                    e3 = exp2_fast(fmaf(c[3], LOG2E, b3));
                } else {
                    e0 = exp2_fast(fmaf(c[0], LOG2E, blc));
                    e1 = exp2_fast(fmaf(c[1], LOG2E, blc));
                    e2 = exp2_fast(fmaf(c[2], LOG2E, blc));
                    e3 = exp2_fast(fmaf(c[3], LOG2E, blc));
                }
                rs0 += e0 + e1;
                rs1 += e2 + e3;
                uint32_t h01 = cvt2(e0, e1), h23 = cvt2(e2, e3);
                pH[np][2 * h]     = h01;
                pH[np][2 * h + 1] = h23;
                pL[np][2 * h]     = cvt2(e0 - bflo(h01), e1 - bfhi(h01));
                pL[np][2 * h + 1] = cvt2(e2 - bflo(h23), e3 - bfhi(h23));
            }
        }

        // stage K(t+1); start V(t+1) loads (arrive under PV MMAs)
        if (t + 1 < NT) {
            SSTORE(KHIB(nbuf), KLOB(nbuf));
            GLOAD(vh, n0 + BN);
        }

        // ---- O += P V ----
#pragma unroll
        for (int s = 0; s < 4; ++s) {
#pragma unroll
            for (int np = 0; np < 4; ++np) {
                uint32_t vH[4], vL[4];
                uint32_t a = sb + (uint32_t)(s * 16 * PITCH + np * 32) + laneV;
                ldsm4t(vH, a + VHIB(buf));
                ldsm4t(vL, a + VLOB(buf));
                mma16816(oc[2 * np],     pH[s], vH);
                mma16816(oc[2 * np + 1], pH[s], vH + 2);
                mma16816(oc[2 * np],     pL[s], vH);
                mma16816(oc[2 * np + 1], pL[s], vH + 2);
                mma16816(oc[2 * np],     pH[s], vL);
                mma16816(oc[2 * np + 1], pH[s], vL + 2);
            }
        }

        if (t + 1 < NT) SSTORE(VHIB(nbuf), VLOB(nbuf));
    }

    // ---- epilogue ----
    float r0 = rs0;
    r0 += __shfl_xor_sync(0xffffffffu, r0, 1);
    r0 += __shfl_xor_sync(0xffffffffu, r0, 2);
    float r1 = rs1;
    r1 += __shfl_xor_sync(0xffffffffu, r1, 1);
    r1 += __shfl_xor_sync(0xffffffffu, r1, 2);
    const float inv0 = 1.0f / r0;
    const float inv1 = 1.0f / r1;

    float* d0 = oh + (size_t)row0 * DH + ccol;
    float* d1 = oh + (size_t)(row0 + 8) * DH + ccol;
#pragma unroll
    for (int nt = 0; nt < 8; ++nt) {
        *(float2*)(d0 + nt * 8) = make_float2(oc[nt][0] * inv0, oc[nt][1] * inv0);
        *(float2*)(d1 + nt * 8) = make_float2(oc[nt][2] * inv1, oc[nt][3] * inv1);
    }
}

extern "C" void kernel_launch(void* const* d_in, const int* in_sizes, int n_in,
                              void* d_out, int out_size) {
    (void)in_sizes; (void)n_in; (void)out_size;
    const float* q    = (const float*)d_in[0];
    const float* k    = (const float*)d_in[1];
    const float* v    = (const float*)d_in[2];
    const float* bias = (const float*)d_in[3];
    float* out = (float*)d_out;

    cudaFuncSetAttribute(relattn_mma, cudaFuncAttributeMaxDynamicSharedMemorySize,
                         SMEM_TOTAL);

    dim3 grid(LSEQ / BM, 2 * 16);   // 32 q-tiles x 32 heads = 1024 CTAs
    relattn_mma<<<grid, NTHR, SMEM_TOTAL>>>(q, k, v, bias, out);
}

// round 5
// speedup vs baseline: 1.1337x; 1.1337x over previous
#include <cuda_runtime.h>
#include <cuda_bf16.h>
#include <cstdint>

// RelativeAttention B=2,H=16,L=2048,D=64 fp32.
// mma.sync bf16 3-way split flash attention, BM=128, warp grid 4(M32) x 2(N32),
// PV split along K with epilogue pair-reduction. Halved ldmatrix traffic vs R3.

#define LSEQ   2048
#define DH     64
#define BM     128
#define BN     64
#define NT     (LSEQ / BN)    // 32
#define NTHR   256
#define MAXREL 8
#define LOG2E  1.4426950408889634f

#define PITCH  144            // bytes per 64-bf16 row
#define BUFHALF 36864
#define OFF_BL  0
#define OFF_BUF 128
#define KHIB(b) (OFF_BUF + (b) * BUFHALF + 0)
#define KLOB(b) (OFF_BUF + (b) * BUFHALF + 9216)
#define VHIB(b) (OFF_BUF + (b) * BUFHALF + 18432)
#define VLOB(b) (OFF_BUF + (b) * BUFHALF + 27648)
#define SMEM_TOTAL (128 + 2 * BUFHALF)   // 73856 B

// epilogue exchange area (reuses KV buffers after final sync)
#define OEXP    272                      // bytes per row (64 f32 + 16B pad)
#define OFF_OEX OFF_BUF
#define OFF_RSX (OFF_BUF + 128 * OEXP)   // 128 floats

// ---------------- helpers ----------------
__device__ __forceinline__ uint32_t s2u(const void* p) {
    uint32_t a;
    asm("{ .reg .u64 t; cvta.to.shared.u64 t, %1; cvt.u32.u64 %0, t; }" : "=r"(a) : "l"(p));
    return a;
}
__device__ __forceinline__ uint32_t cvt2(float lo, float hi) {
    uint32_t d;
    asm("cvt.rn.bf16x2.f32 %0, %1, %2;" : "=r"(d) : "f"(hi), "f"(lo));
    return d;
}
__device__ __forceinline__ float bflo(uint32_t p) { return __int_as_float(p << 16); }
__device__ __forceinline__ float bfhi(uint32_t p) { return __int_as_float(p & 0xFFFF0000u); }

__device__ __forceinline__ void mma16816(float* c, const uint32_t* a, const uint32_t* b) {
    asm volatile(
        "mma.sync.aligned.m16n8k16.row.col.f32.bf16.bf16.f32 "
        "{%0,%1,%2,%3}, {%4,%5,%6,%7}, {%8,%9}, {%0,%1,%2,%3};"
        : "+f"(c[0]), "+f"(c[1]), "+f"(c[2]), "+f"(c[3])
        : "r"(a[0]), "r"(a[1]), "r"(a[2]), "r"(a[3]), "r"(b[0]), "r"(b[1]));
}
__device__ __forceinline__ void ldsm4(uint32_t* r, uint32_t addr) {
    asm volatile("ldmatrix.sync.aligned.m8n8.x4.shared.b16 {%0,%1,%2,%3}, [%4];"
                 : "=r"(r[0]), "=r"(r[1]), "=r"(r[2]), "=r"(r[3]) : "r"(addr));
}
__device__ __forceinline__ void ldsm4t(uint32_t* r, uint32_t addr) {
    asm volatile("ldmatrix.sync.aligned.m8n8.x4.trans.shared.b16 {%0,%1,%2,%3}, [%4];"
                 : "=r"(r[0]), "=r"(r[1]), "=r"(r[2]), "=r"(r[3]) : "r"(addr));
}
__device__ __forceinline__ float exp2_fast(float x) {
    x = fmaxf(x, -100.0f);
    float t = x + 12582912.0f;
    float n = t - 12582912.0f;
    float f = x - n;
    float p = 0.0013333558f;
    p = fmaf(p, f, 0.0096181291f);
    p = fmaf(p, f, 0.0555041090f);
    p = fmaf(p, f, 0.2402265069f);
    p = fmaf(p, f, 0.6931471806f);
    p = fmaf(p, f, 1.0f);
    return __int_as_float(__float_as_int(p) + (__float_as_int(t) << 23));
}
__device__ __forceinline__ void split4(float4 v, uint32_t& h0, uint32_t& h1,
                                       uint32_t& l0, uint32_t& l1) {
    h0 = cvt2(v.x, v.y);
    h1 = cvt2(v.z, v.w);
    l0 = cvt2(v.x - bflo(h0), v.y - bfhi(h0));
    l1 = cvt2(v.z - bflo(h1), v.w - bfhi(h1));
}

// ---------------- kernel ----------------
__global__ void __launch_bounds__(NTHR, 1)
relattn_mma(const float* __restrict__ q, const float* __restrict__ k,
            const float* __restrict__ v, const float* __restrict__ bias,
            float* __restrict__ out) {
    extern __shared__ char smem[];
    const uint32_t sb = s2u(smem);
    float* bl = (float*)(smem + OFF_BL);

    const int tid  = threadIdx.x;
    const int wid  = tid >> 5;
    const int lane = tid & 31;
    const int wm   = wid & 3;            // M-slice 0..3 (32 rows each)
    const int wn   = wid >> 2;           // N/K-half 0..1
    const int head = blockIdx.y;
    const int q0   = blockIdx.x * BM;

    const float* qh = q + (size_t)head * LSEQ * DH;
    const float* kh = k + (size_t)head * LSEQ * DH;
    const float* vh = v + (size_t)head * LSEQ * DH;
    float*       oh = out + (size_t)head * LSEQ * DH;

    if (tid < 2 * MAXREL + 1)
        bl[tid] = (bias[tid] - 12.0f) * LOG2E;

    // ---- Q fragments: warp rows q0 + wm*32 + rb*16 + (lane>>2) {,+8} ----
    const int rloc = wm * 32 + (lane >> 2);      // local row in [0,128)
    const int row0 = q0 + rloc;
    const int ccol = (lane & 3) * 2;
    uint32_t qH[2][4][4], qL[2][4][4];
#pragma unroll
    for (int rb = 0; rb < 2; ++rb)
#pragma unroll
        for (int s = 0; s < 4; ++s) {
            const int r = row0 + rb * 16;
            const int c = s * 16 + ccol;
            float2 x0 = *(const float2*)&qh[(size_t)r * DH + c];
            float2 x1 = *(const float2*)&qh[(size_t)(r + 8) * DH + c];
            float2 x2 = *(const float2*)&qh[(size_t)r * DH + c + 8];
            float2 x3 = *(const float2*)&qh[(size_t)(r + 8) * DH + c + 8];
            float4 a = make_float4(x0.x * 0.125f, x0.y * 0.125f, x1.x * 0.125f, x1.y * 0.125f);
            float4 b = make_float4(x2.x * 0.125f, x2.y * 0.125f, x3.x * 0.125f, x3.y * 0.125f);
            split4(a, qH[rb][s][0], qH[rb][s][1], qL[rb][s][0], qL[rb][s][1]);
            split4(b, qH[rb][s][2], qH[rb][s][3], qL[rb][s][2], qL[rb][s][3]);
        }

    // ---- staging: 256 thr; thread -> row tid>>2 (0..63), 16-col quarter ----
    const int skv = tid >> 2;
    const int sdq = (tid & 3) * 16;
    float4 st[4];

#define GLOAD(base_, n0_) do {                                               \
        const float* p_ = (base_) + (size_t)((n0_) + skv) * DH + sdq;        \
        _Pragma("unroll") for (int i_ = 0; i_ < 4; ++i_)                     \
            st[i_] = *(const float4*)(p_ + i_ * 4);                          \
    } while (0)

#define SSTORE(hiOff_, loOff_) do {                                          \
        char* h_ = smem + (hiOff_); char* l_ = smem + (loOff_);              \
        const int rb_ = skv * PITCH;                                         \
        _Pragma("unroll") for (int i_ = 0; i_ < 4; ++i_) {                   \
            uint32_t h0, h1, l0, l1;                                         \
            split4(st[i_], h0, h1, l0, l1);                                  \
            int o_ = rb_ + (sdq + i_ * 4) * 2;                               \
            *(uint2*)(h_ + o_) = make_uint2(h0, h1);                         \
            *(uint2*)(l_ + o_) = make_uint2(l0, l1);                         \
        } } while (0)

    GLOAD(kh, 0); SSTORE(KHIB(0), KLOB(0));
    GLOAD(vh, 0); SSTORE(VHIB(0), VLOB(0));

    const uint32_t laneK = (uint32_t)(((lane & 7) + ((lane >> 4) & 1) * 8) * PITCH
                                      + ((lane >> 3) & 1) * 16);
    const uint32_t laneV = (uint32_t)(((lane & 7) + ((lane >> 3) & 1) * 8) * PITCH
                                      + ((lane >> 4) & 1) * 16);

    float oc[2][8][4];
#pragma unroll
    for (int rb = 0; rb < 2; ++rb)
#pragma unroll
        for (int i = 0; i < 8; ++i)
#pragma unroll
            for (int j = 0; j < 4; ++j) oc[rb][i][j] = 0.0f;
    float rsum[2][2] = {{0.f, 0.f}, {0.f, 0.f}};

    const int relb = ccol - row0;   // + n0 + wn*32 + nb*8 - rb*16 per element

    for (int t = 0; t < NT; ++t) {
        const int n0 = t * BN;
        const int buf = t & 1;
        const int nbuf = buf ^ 1;

        __syncthreads();                        // buf staged for everyone

        if (t + 1 < NT) GLOAD(kh, n0 + BN);     // K(t+1) inflight under S MMAs

        // ---- S = Q K^T on own N=32 half ----
        float sc[2][4][4];
#pragma unroll
        for (int rb = 0; rb < 2; ++rb)
#pragma unroll
            for (int i = 0; i < 4; ++i)
#pragma unroll
                for (int j = 0; j < 4; ++j) sc[rb][i][j] = 0.0f;

#pragma unroll
        for (int s = 0; s < 4; ++s) {
#pragma unroll
            for (int np = 0; np < 2; ++np) {
                uint32_t bH[4], bL[4];
                uint32_t a = sb + (uint32_t)((wn * 32 + np * 16) * PITCH + s * 32) + laneK;
                ldsm4(bH, a + KHIB(buf));
                ldsm4(bL, a + KLOB(buf));
#pragma unroll
                for (int rb = 0; rb < 2; ++rb) {
                    mma16816(sc[rb][2 * np],     qH[rb][s], bH);
                    mma16816(sc[rb][2 * np + 1], qH[rb][s], bH + 2);
                    mma16816(sc[rb][2 * np],     qL[rb][s], bH);
                    mma16816(sc[rb][2 * np + 1], qL[rb][s], bH + 2);
                    mma16816(sc[rb][2 * np],     qH[rb][s], bL);
                    mma16816(sc[rb][2 * np + 1], qH[rb][s], bL + 2);
                }
            }
        }

        // ---- softmax on own N=32 slice; P fragments from accumulators ----
        const int mx = n0 + BN - 1 - q0;
        const int mn = n0 - (q0 + BM - 1);
        const bool generic = (mx > -MAXREL) && (mn < MAXREL);
        const float blc = (mx <= -MAXREL) ? bl[0] : bl[2 * MAXREL];

        uint32_t pH[2][2][4], pL[2][2][4];      // [rb][ks][frag]
#pragma unroll
        for (int rb = 0; rb < 2; ++rb) {
#pragma unroll
            for (int nb = 0; nb < 4; ++nb) {
                float* c = sc[rb][nb];
                float e0, e1, e2, e3;
                if (generic) {
                    const int r0i = relb + n0 + wn * 32 + nb * 8 - rb * 16;
                    const float b0 = bl[min(max(r0i,     -MAXREL), MAXREL) + MAXREL];
                    const float b1 = bl[min(max(r0i + 1, -MAXREL), MAXREL) + MAXREL];
                    const float b2 = bl[min(max(r0i - 8, -MAXREL), MAXREL) + MAXREL];
                    const float b3 = bl[min(max(r0i - 7, -MAXREL), MAXREL) + MAXREL];
                    e0 = exp2_fast(fmaf(c[0], LOG2E, b0));
                    e1 = exp2_fast(fmaf(c[1], LOG2E, b1));
                    e2 = exp2_fast(fmaf(c[2], LOG2E, b2));
                    e3 = exp2_fast(fmaf(c[3], LOG2E, b3));
                } else {
                    e0 = exp2_fast(fmaf(c[0], LOG2E, blc));
                    e1 = exp2_fast(fmaf(c[1], LOG2E, blc));
                    e2 = exp2_fast(fmaf(c[2], LOG2E, blc));
                    e3 = exp2_fast(fmaf(c[3], LOG2E, blc));
                }
                rsum[rb][0] += e0 + e1;
                rsum[rb][1] += e2 + e3;
                const int ks = nb >> 1, h = nb & 1;
                uint32_t h01 = cvt2(e0, e1), h23 = cvt2(e2, e3);
                pH[rb][ks][2 * h]     = h01;
                pH[rb][ks][2 * h + 1] = h23;
                pL[rb][ks][2 * h]     = cvt2(e0 - bflo(h01), e1 - bfhi(h01));
                pL[rb][ks][2 * h + 1] = cvt2(e2 - bflo(h23), e3 - bfhi(h23));
            }
        }

        if (t + 1 < NT) {
            SSTORE(KHIB(nbuf), KLOB(nbuf));
            GLOAD(vh, n0 + BN);
        }

        // ---- O(partial) += P[:, own 32] * V[own 32, :] ----
#pragma unroll
        for (int ks = 0; ks < 2; ++ks) {
#pragma unroll
            for (int np = 0; np < 4; ++np) {
                uint32_t vH[4], vL[4];
                uint32_t a = sb + (uint32_t)((wn * 32 + ks * 16) * PITCH + np * 32) + laneV;
                ldsm4t(vH, a + VHIB(buf));
                ldsm4t(vL, a + VLOB(buf));
#pragma unroll
                for (int rb = 0; rb < 2; ++rb) {
                    mma16816(oc[rb][2 * np],     pH[rb][ks], vH);
                    mma16816(oc[rb][2 * np + 1], pH[rb][ks], vH + 2);
                    mma16816(oc[rb][2 * np],     pL[rb][ks], vH);
                    mma16816(oc[rb][2 * np + 1], pL[rb][ks], vH + 2);
                    mma16816(oc[rb][2 * np],     pH[rb][ks], vL);
                    mma16816(oc[rb][2 * np + 1], pH[rb][ks], vL + 2);
                }
            }
        }

        if (t + 1 < NT) SSTORE(VHIB(nbuf), VLOB(nbuf));
    }

    // ---- epilogue: pair-reduce (wn=0) + (wn=1), normalize, store ----
    // reduce rowsums across the 4 lanes of each row group
#pragma unroll
    for (int rb = 0; rb < 2; ++rb)
#pragma unroll
        for (int h = 0; h < 2; ++h) {
            float r = rsum[rb][h];
            r += __shfl_xor_sync(0xffffffffu, r, 1);
            r += __shfl_xor_sync(0xffffffffu, r, 2);
            rsum[rb][h] = r;
        }

    __syncthreads();   // all MMAs done; safe to reuse KV smem
    if (wn == 1) {
#pragma unroll
        for (int rb = 0; rb < 2; ++rb) {
            const int r = rloc + rb * 16;
            char* base0 = smem + OFF_OEX + r * OEXP + ccol * 4;
            char* base1 = smem + OFF_OEX + (r + 8) * OEXP + ccol * 4;
#pragma unroll
            for (int nt = 0; nt < 8; ++nt) {
                *(float2*)(base0 + nt * 32) = make_float2(oc[rb][nt][0], oc[rb][nt][1]);
                *(float2*)(base1 + nt * 32) = make_float2(oc[rb][nt][2], oc[rb][nt][3]);
            }
            if ((lane & 3) == 0) {
                ((float*)(smem + OFF_RSX))[r]     = rsum[rb][0];
                ((float*)(smem + OFF_RSX))[r + 8] = rsum[rb][1];
            }
        }
    }
    __syncthreads();
    if (wn == 0) {
        const float* rsx = (const float*)(smem + OFF_RSX);
#pragma unroll
        for (int rb = 0; rb < 2; ++rb) {
            const int r = rloc + rb * 16;
            const float inv0 = 1.0f / (rsum[rb][0] + rsx[r]);
            const float inv1 = 1.0f / (rsum[rb][1] + rsx[r + 8]);
            const char* base0 = smem + OFF_OEX + r * OEXP + ccol * 4;
            const char* base1 = smem + OFF_OEX + (r + 8) * OEXP + ccol * 4;
            float* d0 = oh + (size_t)(row0 + rb * 16) * DH + ccol;
            float* d1 = d0 + 8 * DH;
#pragma unroll
            for (int nt = 0; nt < 8; ++nt) {
                float2 x0 = *(const float2*)(base0 + nt * 32);
                float2 x1 = *(const float2*)(base1 + nt * 32);
                *(float2*)(d0 + nt * 8) =
                    make_float2((oc[rb][nt][0] + x0.x) * inv0, (oc[rb][nt][1] + x0.y) * inv0);
                *(float2*)(d1 + nt * 8) =
                    make_float2((oc[rb][nt][2] + x1.x) * inv1, (oc[rb][nt][3] + x1.y) * inv1);
            }
        }
    }
}

extern "C" void kernel_launch(void* const* d_in, const int* in_sizes, int n_in,
                              void* d_out, int out_size) {
    (void)in_sizes; (void)n_in; (void)out_size;
    const float* q    = (const float*)d_in[0];
    const float* k    = (const float*)d_in[1];
    const float* v    = (const float*)d_in[2];
    const float* bias = (const float*)d_in[3];
    float* out = (float*)d_out;

    cudaFuncSetAttribute(relattn_mma, cudaFuncAttributeMaxDynamicSharedMemorySize,
                         SMEM_TOTAL);

    dim3 grid(LSEQ / BM, 2 * 16);   // 16 q-tiles x 32 heads = 512 CTAs
    relattn_mma<<<grid, NTHR, SMEM_TOTAL>>>(q, k, v, bias, out);
}

// round 6
// speedup vs baseline: 1.2051x; 1.0630x over previous
#include <cuda_runtime.h>
#include <cuda_bf16.h>
#include <cstdint>

// RelativeAttention B=2,H=16,L=2048,D=64 fp32.
// mma.sync bf16 3-way split flash attention. BM=128, 128 threads (4 warps, M32xN64),
// 2 independent CTAs/SM for phase desynchronization. Fused exp.

#define LSEQ   2048
#define DH     64
#define BM     128
#define BN     64
#define NT     (LSEQ / BN)    // 32
#define NTHR   128
#define MAXREL 8
#define LOG2E  1.4426950408889634f

#define PITCH  144
#define BUFHALF 36864
#define OFF_BL  0
#define OFF_BUF 128
#define KHIB(b) (OFF_BUF + (b) * BUFHALF + 0)
#define KLOB(b) (OFF_BUF + (b) * BUFHALF + 9216)
#define VHIB(b) (OFF_BUF + (b) * BUFHALF + 18432)
#define VLOB(b) (OFF_BUF + (b) * BUFHALF + 27648)
#define SMEM_TOTAL (128 + 2 * BUFHALF)   // 73856 B/CTA, 2 CTAs = 147.7 KB/SM

// ---------------- helpers ----------------
__device__ __forceinline__ uint32_t s2u(const void* p) {
    uint32_t a;
    asm("{ .reg .u64 t; cvta.to.shared.u64 t, %1; cvt.u32.u64 %0, t; }" : "=r"(a) : "l"(p));
    return a;
}
__device__ __forceinline__ uint32_t cvt2(float lo, float hi) {
    uint32_t d;
    asm("cvt.rn.bf16x2.f32 %0, %1, %2;" : "=r"(d) : "f"(hi), "f"(lo));
    return d;
}
__device__ __forceinline__ float bflo(uint32_t p) { return __int_as_float(p << 16); }
__device__ __forceinline__ float bfhi(uint32_t p) { return __int_as_float(p & 0xFFFF0000u); }

__device__ __forceinline__ void mma16816(float* c, const uint32_t* a, const uint32_t* b) {
    asm volatile(
        "mma.sync.aligned.m16n8k16.row.col.f32.bf16.bf16.f32 "
        "{%0,%1,%2,%3}, {%4,%5,%6,%7}, {%8,%9}, {%0,%1,%2,%3};"
        : "+f"(c[0]), "+f"(c[1]), "+f"(c[2]), "+f"(c[3])
        : "r"(a[0]), "r"(a[1]), "r"(a[2]), "r"(a[3]), "r"(b[0]), "r"(b[1]));
}
__device__ __forceinline__ void ldsm4(uint32_t* r, uint32_t addr) {
    asm volatile("ldmatrix.sync.aligned.m8n8.x4.shared.b16 {%0,%1,%2,%3}, [%4];"
                 : "=r"(r[0]), "=r"(r[1]), "=r"(r[2]), "=r"(r[3]) : "r"(addr));
}
__device__ __forceinline__ void ldsm4t(uint32_t* r, uint32_t addr) {
    asm volatile("ldmatrix.sync.aligned.m8n8.x4.trans.shared.b16 {%0,%1,%2,%3}, [%4];"
                 : "=r"(r[0]), "=r"(r[1]), "=r"(r[2]), "=r"(r[3]) : "r"(addr));
}
__device__ __forceinline__ float exp2_fast(float x) {
    x = fmaxf(x, -100.0f);
    float t = x + 12582912.0f;
    float n = t - 12582912.0f;
    float f = x - n;
    float p = 0.0013333558f;
    p = fmaf(p, f, 0.0096181291f);
    p = fmaf(p, f, 0.0555041090f);
    p = fmaf(p, f, 0.2402265069f);
    p = fmaf(p, f, 0.6931471806f);
    p = fmaf(p, f, 1.0f);
    return __int_as_float(__float_as_int(p) + (__float_as_int(t) << 23));
}
__device__ __forceinline__ void split4(float4 v, uint32_t& h0, uint32_t& h1,
                                       uint32_t& l0, uint32_t& l1) {
    h0 = cvt2(v.x, v.y);
    h1 = cvt2(v.z, v.w);
    l0 = cvt2(v.x - bflo(h0), v.y - bfhi(h0));
    l1 = cvt2(v.z - bflo(h1), v.w - bfhi(h1));
}

// ---------------- kernel ----------------
__global__ void __launch_bounds__(NTHR, 2)
relattn_mma(const float* __restrict__ q, const float* __restrict__ k,
            const float* __restrict__ v, const float* __restrict__ bias,
            float* __restrict__ out) {
    extern __shared__ char smem[];
    const uint32_t sb = s2u(smem);
    float* bl = (float*)(smem + OFF_BL);

    const int tid  = threadIdx.x;
    const int wid  = tid >> 5;            // 0..3, M-slice of 32 rows
    const int lane = tid & 31;
    const int head = blockIdx.y;
    const int q0   = blockIdx.x * BM;

    const float* qh = q + (size_t)head * LSEQ * DH;
    const float* kh = k + (size_t)head * LSEQ * DH;
    const float* vh = v + (size_t)head * LSEQ * DH;
    float*       oh = out + (size_t)head * LSEQ * DH;

    if (tid < 2 * MAXREL + 1)
        bl[tid] = (bias[tid] - 12.0f) * LOG2E;

    // ---- Q fragments (persistent hi/lo): rows q0 + wid*32 + rb*16 + ... ----
    const int row0 = q0 + wid * 32 + (lane >> 2);
    const int ccol = (lane & 3) * 2;
    uint32_t qH[2][4][4], qL[2][4][4];
#pragma unroll
    for (int rb = 0; rb < 2; ++rb)
#pragma unroll
        for (int s = 0; s < 4; ++s) {
            const int r = row0 + rb * 16;
            const int c = s * 16 + ccol;
            float2 x0 = *(const float2*)&qh[(size_t)r * DH + c];
            float2 x1 = *(const float2*)&qh[(size_t)(r + 8) * DH + c];
            float2 x2 = *(const float2*)&qh[(size_t)r * DH + c + 8];
            float2 x3 = *(const float2*)&qh[(size_t)(r + 8) * DH + c + 8];
            float4 a = make_float4(x0.x * 0.125f, x0.y * 0.125f, x1.x * 0.125f, x1.y * 0.125f);
            float4 b = make_float4(x2.x * 0.125f, x2.y * 0.125f, x3.x * 0.125f, x3.y * 0.125f);
            split4(a, qH[rb][s][0], qH[rb][s][1], qL[rb][s][0], qL[rb][s][1]);
            split4(b, qH[rb][s][2], qH[rb][s][3], qL[rb][s][2], qL[rb][s][3]);
        }

    // ---- staging: 128 thr; thread -> kv row tid>>1 (0..63), 32-col half ----
    const int skv = tid >> 1;
    const int sdq = (tid & 1) * 32;
    float4 st[8];

#define GLOAD(base_, n0_) do {                                               \
        const float* p_ = (base_) + (size_t)((n0_) + skv) * DH + sdq;        \
        _Pragma("unroll") for (int i_ = 0; i_ < 8; ++i_)                     \
            st[i_] = *(const float4*)(p_ + i_ * 4);                          \
    } while (0)

#define SSTORE(hiOff_, loOff_) do {                                          \
        char* h_ = smem + (hiOff_); char* l_ = smem + (loOff_);              \
        const int rb_ = skv * PITCH;                                         \
        _Pragma("unroll") for (int i_ = 0; i_ < 8; ++i_) {                   \
            uint32_t h0, h1, l0, l1;                                         \
            split4(st[i_], h0, h1, l0, l1);                                  \
            int o_ = rb_ + (sdq + i_ * 4) * 2;                               \
            *(uint2*)(h_ + o_) = make_uint2(h0, h1);                         \
            *(uint2*)(l_ + o_) = make_uint2(l0, l1);                         \
        } } while (0)

    GLOAD(kh, 0); SSTORE(KHIB(0), KLOB(0));
    GLOAD(vh, 0); SSTORE(VHIB(0), VLOB(0));

    const uint32_t laneK = (uint32_t)(((lane & 7) + ((lane >> 4) & 1) * 8) * PITCH
                                      + ((lane >> 3) & 1) * 16);
    const uint32_t laneV = (uint32_t)(((lane & 7) + ((lane >> 3) & 1) * 8) * PITCH
                                      + ((lane >> 4) & 1) * 16);

    float oc[2][8][4];
#pragma unroll
    for (int rb = 0; rb < 2; ++rb)
#pragma unroll
        for (int i = 0; i < 8; ++i)
#pragma unroll
            for (int j = 0; j < 4; ++j) oc[rb][i][j] = 0.0f;
    float rsum[2][2] = {{0.f, 0.f}, {0.f, 0.f}};
    const int relb = ccol - row0;

    for (int t = 0; t < NT; ++t) {
        const int n0 = t * BN;
        const int buf = t & 1;
        const int nbuf = buf ^ 1;

        __syncthreads();                        // buf staged

        if (t + 1 < NT) GLOAD(kh, n0 + BN);     // K(t+1) inflight under S MMAs

        const int mx = n0 + BN - 1 - q0;
        const int mn = n0 - (q0 + BM - 1);
        const bool generic = (mx > -MAXREL) && (mn < MAXREL);
        const float blc = (mx <= -MAXREL) ? bl[0] : bl[2 * MAXREL];

        // ---- S = Q K^T fused with exp, np-chunks of 16 cols ----
        uint32_t pH[2][4][4], pL[2][4][4];      // [rb][ks=np][a-frag]
#pragma unroll
        for (int np = 0; np < 4; ++np) {
            float se[2][4], so[2][4];
#pragma unroll
            for (int rb = 0; rb < 2; ++rb)
#pragma unroll
                for (int j = 0; j < 4; ++j) { se[rb][j] = 0.f; so[rb][j] = 0.f; }
#pragma unroll
            for (int s = 0; s < 4; ++s) {
                uint32_t bH[4], bL[4];
                uint32_t a = sb + (uint32_t)(np * 16 * PITCH + s * 32) + laneK;
                ldsm4(bH, a + KHIB(buf));
                ldsm4(bL, a + KLOB(buf));
#pragma unroll
                for (int rb = 0; rb < 2; ++rb) {
                    mma16816(se[rb], qH[rb][s], bH);
                    mma16816(so[rb], qH[rb][s], bH + 2);
                    mma16816(se[rb], qL[rb][s], bH);
                    mma16816(so[rb], qL[rb][s], bH + 2);
                    mma16816(se[rb], qH[rb][s], bL);
                    mma16816(so[rb], qH[rb][s], bL + 2);
                }
            }
            // exp for this 16-col chunk (overlaps next np's MMAs / other CTA)
#pragma unroll
            for (int rb = 0; rb < 2; ++rb) {
#pragma unroll
                for (int h = 0; h < 2; ++h) {
                    float* c = h ? so[rb] : se[rb];
                    float e0, e1, e2, e3;
                    if (generic) {
                        const int r0i = relb + n0 + (2 * np + h) * 8 - rb * 16;
                        const float b0 = bl[min(max(r0i,     -MAXREL), MAXREL) + MAXREL];
                        const float b1 = bl[min(max(r0i + 1, -MAXREL), MAXREL) + MAXREL];
                        const float b2 = bl[min(max(r0i - 8, -MAXREL), MAXREL) + MAXREL];
                        const float b3 = bl[min(max(r0i - 7, -MAXREL), MAXREL) + MAXREL];
                        e0 = exp2_fast(fmaf(c[0], LOG2E, b0));
                        e1 = exp2_fast(fmaf(c[1], LOG2E, b1));
                        e2 = exp2_fast(fmaf(c[2], LOG2E, b2));
                        e3 = exp2_fast(fmaf(c[3], LOG2E, b3));
                    } else {
                        e0 = exp2_fast(fmaf(c[0], LOG2E, blc));
                        e1 = exp2_fast(fmaf(c[1], LOG2E, blc));
                        e2 = exp2_fast(fmaf(c[2], LOG2E, blc));
                        e3 = exp2_fast(fmaf(c[3], LOG2E, blc));
                    }
                    rsum[rb][0] += e0 + e1;
                    rsum[rb][1] += e2 + e3;
                    uint32_t h01 = cvt2(e0, e1), h23 = cvt2(e2, e3);
                    pH[rb][np][2 * h]     = h01;
                    pH[rb][np][2 * h + 1] = h23;
                    pL[rb][np][2 * h]     = cvt2(e0 - bflo(h01), e1 - bfhi(h01));
                    pL[rb][np][2 * h + 1] = cvt2(e2 - bflo(h23), e3 - bfhi(h23));
                }
            }
        }

        if (t + 1 < NT) {
            SSTORE(KHIB(nbuf), KLOB(nbuf));
            GLOAD(vh, n0 + BN);                 // V(t+1) inflight under PV MMAs
        }

        // ---- O += P V ----
#pragma unroll
        for (int ks = 0; ks < 4; ++ks) {
#pragma unroll
            for (int np = 0; np < 4; ++np) {
                uint32_t vH[4], vL[4];
                uint32_t a = sb + (uint32_t)(ks * 16 * PITCH + np * 32) + laneV;
                ldsm4t(vH, a + VHIB(buf));
                ldsm4t(vL, a + VLOB(buf));
#pragma unroll
                for (int rb = 0; rb < 2; ++rb) {
                    mma16816(oc[rb][2 * np],     pH[rb][ks], vH);
                    mma16816(oc[rb][2 * np + 1], pH[rb][ks], vH + 2);
                    mma16816(oc[rb][2 * np],     pL[rb][ks], vH);
                    mma16816(oc[rb][2 * np + 1], pL[rb][ks], vH + 2);
                    mma16816(oc[rb][2 * np],     pH[rb][ks], vL);
                    mma16816(oc[rb][2 * np + 1], pH[rb][ks], vL + 2);
                }
            }
        }

        if (t + 1 < NT) SSTORE(VHIB(nbuf), VLOB(nbuf));
    }

    // ---- epilogue: reduce rowsums over quad lanes, normalize, store ----
#pragma unroll
    for (int rb = 0; rb < 2; ++rb)
#pragma unroll
        for (int h = 0; h < 2; ++h) {
            float r = rsum[rb][h];
            r += __shfl_xor_sync(0xffffffffu, r, 1);
            r += __shfl_xor_sync(0xffffffffu, r, 2);
            rsum[rb][h] = r;
        }

#pragma unroll
    for (int rb = 0; rb < 2; ++rb) {
        const float inv0 = 1.0f / rsum[rb][0];
        const float inv1 = 1.0f / rsum[rb][1];
        float* d0 = oh + (size_t)(row0 + rb * 16) * DH + ccol;
        float* d1 = d0 + 8 * DH;
#pragma unroll
        for (int nt = 0; nt < 8; ++nt) {
            *(float2*)(d0 + nt * 8) = make_float2(oc[rb][nt][0] * inv0, oc[rb][nt][1] * inv0);
            *(float2*)(d1 + nt * 8) = make_float2(oc[rb][nt][2] * inv1, oc[rb][nt][3] * inv1);
        }
    }
}

extern "C" void kernel_launch(void* const* d_in, const int* in_sizes, int n_in,
                              void* d_out, int out_size) {
    (void)in_sizes; (void)n_in; (void)out_size;
    const float* q    = (const float*)d_in[0];
    const float* k    = (const float*)d_in[1];
    const float* v    = (const float*)d_in[2];
    const float* bias = (const float*)d_in[3];
    float* out = (float*)d_out;

    cudaFuncSetAttribute(relattn_mma, cudaFuncAttributeMaxDynamicSharedMemorySize,
                         SMEM_TOTAL);

    dim3 grid(LSEQ / BM, 2 * 16);   // 16 q-tiles x 32 heads = 512 CTAs
    relattn_mma<<<grid, NTHR, SMEM_TOTAL>>>(q, k, v, bias, out);
}